// round 15
// baseline (speedup 1.0000x reference)
#include <cuda_runtime.h>
#include <cstdint>

#define T_STEPS 1024
#define BATCH   64
#define DIN     256
#define HID     512
#define OUTD    256
#define G3      1536   // 3*HID

// ---------------- persistent scratch (device globals; no allocation) ----------
__device__ float g_xg[(size_t)T_STEPS * BATCH * G3];   // ~402 MB
__device__ float g_hs[(size_t)T_STEPS * BATCH * HID];  // ~134 MB
__device__ __align__(256) float g_h[2][HID * BATCH];   // k-major: [512][64]
__device__ unsigned int g_bar;

// ---------------- packed f32x2 + async helpers --------------------------------
__device__ __forceinline__ void fma2(uint64_t& d, uint64_t a, uint64_t b) {
    asm("fma.rn.f32x2 %0, %1, %2, %0;" : "+l"(d) : "l"(a), "l"(b));
}
__device__ __forceinline__ uint64_t pack2(float lo, float hi) {
    uint64_t r;
    asm("mov.b64 %0, {%1, %2};" : "=l"(r) : "f"(lo), "f"(hi));
    return r;
}
__device__ __forceinline__ float2 unpack2(uint64_t v) {
    float2 f;
    asm("mov.b64 {%0, %1}, %2;" : "=f"(f.x), "=f"(f.y) : "l"(v));
    return f;
}
__device__ __forceinline__ uint32_t smem_u32(const void* p) {
    uint32_t a;
    asm("{ .reg .u64 t; cvta.to.shared.u64 t, %1; cvt.u32.u64 %0, t; }"
        : "=r"(a) : "l"(p));
    return a;
}
__device__ __forceinline__ void mbar_init(uint32_t mbar, uint32_t cnt) {
    asm volatile("mbarrier.init.shared.b64 [%0], %1;" :: "r"(mbar), "r"(cnt) : "memory");
}
__device__ __forceinline__ void mbar_expect_tx(uint32_t mbar, uint32_t bytes) {
    asm volatile("mbarrier.arrive.expect_tx.shared.b64 _, [%0], %1;"
                 :: "r"(mbar), "r"(bytes) : "memory");
}
__device__ __forceinline__ void mbar_wait(uint32_t mbar, uint32_t parity) {
    asm volatile(
        "{\n\t.reg .pred P;\n"
        "WL%=:\n\t"
        "mbarrier.try_wait.parity.acquire.cta.shared::cta.b64 P, [%0], %1, 0x989680;\n\t"
        "@P bra WD%=;\n\t"
        "bra WL%=;\n"
        "WD%=:\n\t}"
        :: "r"(mbar), "r"(parity) : "memory");
}
__device__ __forceinline__ void bulk_g2s_mc(uint32_t dst, const void* src,
                                            uint32_t bytes, uint32_t mbar,
                                            uint16_t mask) {
    asm volatile(
        "cp.async.bulk.shared::cluster.global.mbarrier::complete_tx::bytes"
        ".multicast::cluster [%0], [%1], %2, [%3], %4;"
        :: "r"(dst), "l"(src), "r"(bytes), "r"(mbar), "h"(mask) : "memory");
}
// fence-free grid barrier primitives
__device__ __forceinline__ void bar_arrive_release(unsigned int* p) {
    asm volatile("red.release.gpu.global.add.u32 [%0], 1;" :: "l"(p) : "memory");
}
__device__ __forceinline__ unsigned bar_load_acquire(unsigned int* p) {
    unsigned v;
    asm volatile("ld.acquire.gpu.global.u32 %0, [%1];" : "=r"(v) : "l"(p) : "memory");
    return v;
}

// =============================================================================
// SGEMM with bias: C[M,N] = A[M,K] @ B[K,N] + bias[N]
// 128x128 tile, BK=16, 256 threads, 2 CTAs/SM (latency overlap across CTAs).
// =============================================================================
__global__ void __launch_bounds__(256, 2) sgemm_bias(
    const float* __restrict__ A, const float* __restrict__ B,
    const float* __restrict__ bias, float* __restrict__ C,
    int M, int N, int K)
{
    constexpr int BM = 128, BN = 128, BK = 16;
    __shared__ __align__(16) float As[BK][BM];
    __shared__ __align__(16) float Bs[BK][BN];

    const int tid  = threadIdx.x;
    const int w    = tid >> 5;
    const int lane = tid & 31;
    const int r    = (lane >> 3) + ((w >> 1) << 2);
    const int c    = (lane & 7) + ((w & 1) << 3);
    const int trow = r * 8;
    const int tc1  = c * 4;
    const int tc2  = c * 4 + 64;
    const int bm   = blockIdx.y * BM;
    const int bn   = blockIdx.x * BN;

    uint64_t acc[8][4];
#pragma unroll
    for (int i = 0; i < 8; i++)
#pragma unroll
        for (int j = 0; j < 4; j++) acc[i][j] = 0ull;

    for (int k0 = 0; k0 < K; k0 += BK) {
#pragma unroll
        for (int l = 0; l < 2; l++) {
            int cc  = tid * 2 + l;
            int row = cc >> 2;
            int kq  = (cc & 3) * 4;
            float4 v = *(const float4*)(A + (size_t)(bm + row) * K + k0 + kq);
            As[kq + 0][row] = v.x;
            As[kq + 1][row] = v.y;
            As[kq + 2][row] = v.z;
            As[kq + 3][row] = v.w;
        }
#pragma unroll
        for (int l = 0; l < 2; l++) {
            int cc = tid + (l << 8);
            int kr = cc >> 5;
            int n4 = (cc & 31) * 4;
            *(float4*)&Bs[kr][n4] =
                *(const float4*)(B + (size_t)(k0 + kr) * N + bn + n4);
        }
        __syncthreads();

#pragma unroll
        for (int kk = 0; kk < BK; kk++) {
            float4 a0 = *(const float4*)&As[kk][trow];
            float4 a1 = *(const float4*)&As[kk][trow + 4];
            ulonglong2 b01 = *(const ulonglong2*)&Bs[kk][tc1];
            ulonglong2 b23 = *(const ulonglong2*)&Bs[kk][tc2];
            float af[8] = {a0.x, a0.y, a0.z, a0.w, a1.x, a1.y, a1.z, a1.w};
#pragma unroll
            for (int i = 0; i < 8; i++) {
                uint64_t ad = pack2(af[i], af[i]);
                fma2(acc[i][0], ad, b01.x);
                fma2(acc[i][1], ad, b01.y);
                fma2(acc[i][2], ad, b23.x);
                fma2(acc[i][3], ad, b23.y);
            }
        }
        __syncthreads();
    }

    float bv1[4], bv2[4];
#pragma unroll
    for (int j = 0; j < 4; j++) {
        bv1[j] = bias[bn + tc1 + j];
        bv2[j] = bias[bn + tc2 + j];
    }

#pragma unroll
    for (int i = 0; i < 8; i++) {
        float2 p0 = unpack2(acc[i][0]);
        float2 p1 = unpack2(acc[i][1]);
        float2 p2 = unpack2(acc[i][2]);
        float2 p3 = unpack2(acc[i][3]);
        size_t row = (size_t)(bm + trow + i) * N + bn;
        *(float4*)(C + row + tc1) = make_float4(p0.x + bv1[0], p0.y + bv1[1],
                                                p1.x + bv1[2], p1.y + bv1[3]);
        *(float4*)(C + row + tc2) = make_float4(p2.x + bv2[0], p2.y + bv2[1],
                                                p3.x + bv2[2], p3.y + bv2[3]);
    }
}

// =============================================================================
// Persistent GRU scan v7 — k-major h + 4-slice staggered multicast.
//
// h stored k-major [512][64]. Rank r of each 4-CTA cluster multicasts k-slice
// r (128 rows, 32KB) to mbar[r] in all 4 CTAs. Warp kq (k in [kq*32,kq*32+32))
// waits ONLY mbar[kq/4] -> compute starts on first slice arrival, overlapping
// the rest of the broadcast. Fence-free red.release/ld.acquire grid barrier.
// Thread = (lane bb: batches bb & bb+32, warp kq). FMA floor unchanged.
// =============================================================================
#define NT    512
#define RPAD2 193                                 // 16*12 + 1
#define HS_FLOATS  (HID * BATCH)                  // 32768
#define WS_FLOATS  (2 * 256 * 12)                 // 6144
#define RED_FLOATS (BATCH * RPAD2)                // 12352
#define SCAN_SMEM  ((HS_FLOATS + WS_FLOATS + RED_FLOATS) * 4 + 32)  // 205088 B
#define SLICE_BYTES (128 * BATCH * 4)             // 32768 (128 k-rows)

__global__ void __launch_bounds__(NT, 1) __cluster_dims__(4, 1, 1)
gru_scan(const float* __restrict__ Wh, const float* __restrict__ bhn)
{
    extern __shared__ float smem[];
    float*  h_sm = smem;                                  // [512][64] k-major
    float2* wsm2 = (float2*)(smem + HS_FLOATS);           // [256 kp][12 c]
    float*  red  = smem + HS_FLOATS + WS_FLOATS;          // [64][RPAD2]
    uint64_t* mbar = (uint64_t*)(smem + HS_FLOATS + WS_FLOATS + RED_FLOATS);

    const int tid = threadIdx.x;
    const int j0  = blockIdx.x * 4;

    uint32_t rank;
    asm("mov.u32 %0, %%cluster_ctarank;" : "=r"(rank));

    const uint32_t h_sm_a = smem_u32(h_sm);
    uint32_t mba[4];
#pragma unroll
    for (int s = 0; s < 4; s++) mba[s] = smem_u32(&mbar[s]);

    if (tid == 0)
#pragma unroll
        for (int s = 0; s < 4; s++) mbar_init(mba[s], 1);

    // one-time W load, k-pair interleaved: wsm2[kp*12+c] = (W[2kp,c],W[2kp+1,c])
    for (int i = tid; i < 256 * 12; i += NT) {
        int kp = i / 12, cc = i % 12;
        int jl = cc / 3, g = cc - jl * 3;
        int col = g * HID + j0 + jl;
        float2 v;
        v.x = Wh[(size_t)(2 * kp)     * G3 + col];
        v.y = Wh[(size_t)(2 * kp + 1) * G3 + col];
        wsm2[i] = v;
    }
    __syncthreads();
    asm volatile("barrier.cluster.arrive.aligned;" ::: "memory");
    asm volatile("barrier.cluster.wait.aligned;" ::: "memory");

    const int bb  = tid & 31;         // compute role: batches bb, bb+32
    const int kq  = tid >> 5;         // compute role: k-segment (0..15)
    const uint32_t mymb = mba[kq >> 2];
    const int rb  = tid >> 2;         // reducer role: batch (tid < 256)
    const int rjl = tid & 3;          // reducer role: local j
    const float bh = bhn[j0 + rjl];

    const float*  hbase = h_sm + kq * 32 * BATCH + bb;   // k-major walk
    const float2* wbase = wsm2 + (size_t)kq * 16 * 12;

    const unsigned nblk = gridDim.x;

    for (int t = 0; t < T_STEPS; t++) {
        const float* hread  = g_h[t & 1];
        float*       hwrite = g_h[(t & 1) ^ 1];

        if (tid == 0) {
            // expect BEFORE barrier arrive: no tx can land earlier
#pragma unroll
            for (int s = 0; s < 4; s++) mbar_expect_tx(mba[s], SLICE_BYTES);
            bar_arrive_release(&g_bar);
            unsigned target = nblk * (unsigned)(t + 1);
            while (bar_load_acquire(&g_bar) < target) { }
            // multicast my rank's k-slice to all 4 cluster CTAs
            bulk_g2s_mc(h_sm_a + rank * SLICE_BYTES,
                        (const char*)hread + rank * SLICE_BYTES,
                        SLICE_BYTES, mba[rank], (uint16_t)0xF);
        }

        // reducer xg prefetch (DRAM latency hides under barrier/copy)
        float xr = 0.f, xz = 0.f, xn = 0.f;
        if (tid < 256) {
            size_t xb = ((size_t)t * BATCH + rb) * G3 + j0 + rjl;
            xr = __ldcg(&g_xg[xb]);
            xz = __ldcg(&g_xg[xb + HID]);
            xn = __ldcg(&g_xg[xb + 2 * HID]);
        }

        // wait only MY k-slice
        mbar_wait(mymb, t & 1);

        uint64_t accA[12], accB[12];
#pragma unroll
        for (int cc = 0; cc < 12; cc++) { accA[cc] = 0ull; accB[cc] = 0ull; }

#pragma unroll
        for (int i = 0; i < 16; i++) {            // one k-pair per i
            const float* hk = hbase + i * 2 * BATCH;
            uint64_t hA = pack2(hk[0],          hk[BATCH]);          // b=bb
            uint64_t hB = pack2(hk[32],         hk[BATCH + 32]);     // b=bb+32
            const ulonglong2* w6 = (const ulonglong2*)(wbase + i * 12);
#pragma unroll
            for (int m = 0; m < 6; m++) {
                ulonglong2 wv = w6[m];
                fma2(accA[2 * m],     hA, wv.x);
                fma2(accA[2 * m + 1], hA, wv.y);
                fma2(accB[2 * m],     hB, wv.x);
                fma2(accB[2 * m + 1], hB, wv.y);
            }
        }

        // partials: red[b][kq*12+c]
#pragma unroll
        for (int cc = 0; cc < 12; cc++) {
            float2 v = unpack2(accA[cc]);
            red[bb * RPAD2 + kq * 12 + cc] = v.x + v.y;
        }
#pragma unroll
        for (int cc = 0; cc < 12; cc++) {
            float2 v = unpack2(accB[cc]);
            red[(bb + 32) * RPAD2 + kq * 12 + cc] = v.x + v.y;
        }
        __syncthreads();

        // reduce 16 k-segments, gate, store
        if (tid < 256) {
            float hr = 0.f, hz = 0.f, hn = 0.f;
#pragma unroll
            for (int q = 0; q < 16; q++) {
                const float* rp = red + rb * RPAD2 + q * 12 + rjl * 3;
                hr += rp[0];
                hz += rp[1];
                hn += rp[2];
            }
            float rg = 1.f / (1.f + __expf(-(xr + hr)));
            float zg = 1.f / (1.f + __expf(-(xz + hz)));
            float ng = tanhf(xn + rg * (hn + bh));
            float hp = h_sm[(j0 + rjl) * BATCH + rb];
            float hnew = (1.f - zg) * ng + zg * hp;

            hwrite[(j0 + rjl) * BATCH + rb] = hnew;                  // k-major
            g_hs[((size_t)t * BATCH + rb) * HID + j0 + rjl] = hnew;  // b-major
        }
        __syncthreads();   // all h_sm reads + stores done before next arrive
    }

    asm volatile("barrier.cluster.arrive.aligned;" ::: "memory");
    asm volatile("barrier.cluster.wait.aligned;" ::: "memory");
}

// seed h0 (b-major input) into k-major g_h[0]
__global__ void seed_h0(const float* __restrict__ h0) {
    int i = blockIdx.x * 256 + threadIdx.x;      // over 64*512
    int b = i >> 9, j = i & 511;
    g_h[0][j * BATCH + b] = h0[b * HID + j];
}

// no-op: shifts ncu's -s5-c1 window so launch #6 == gru_scan
__global__ void pad_noop() {}

// =============================================================================
extern "C" void kernel_launch(void* const* d_in, const int* in_sizes, int n_in,
                              void* d_out, int out_size)
{
    const float* x   = (const float*)d_in[0];
    const float* Wi  = (const float*)d_in[1];
    const float* bi  = (const float*)d_in[2];
    const float* Wh  = (const float*)d_in[3];
    const float* bhn = (const float*)d_in[4];
    const float* Wo  = (const float*)d_in[5];
    const float* bo  = (const float*)d_in[6];
    const float* h0  = (const float*)d_in[7];
    float* out = (float*)d_out;

    void *xg_p, *hs_p, *bar_p;
    cudaGetSymbolAddress(&xg_p, g_xg);
    cudaGetSymbolAddress(&hs_p, g_hs);
    cudaGetSymbolAddress(&bar_p, g_bar);

    cudaFuncSetAttribute(gru_scan, cudaFuncAttributeMaxDynamicSharedMemorySize,
                         SCAN_SMEM);

    cudaMemsetAsync(bar_p, 0, sizeof(unsigned), 0);                  // launch 1
    seed_h0<<<128, 256>>>(h0);                                       // launch 2

    // 1) xg = x @ Wi + bi
    {
        dim3 grid(G3 / 128, (T_STEPS * BATCH) / 128);
        sgemm_bias<<<grid, 256>>>(x, Wi, bi, (float*)xg_p,
                                  T_STEPS * BATCH, G3, DIN);         // launch 3
    }

    pad_noop<<<1, 32>>>();                                           // launch 4
    pad_noop<<<1, 32>>>();                                           // launch 5

    // 2) persistent GRU scan (32 clusters of 4)
    gru_scan<<<HID / 4, NT, SCAN_SMEM>>>(Wh, bhn);                   // launch 6

    // 3) out = hs @ Wo + bo
    {
        dim3 grid(OUTD / 128, (T_STEPS * BATCH) / 128);
        sgemm_bias<<<grid, 256>>>((const float*)hs_p, Wo, bo, out,
                                  T_STEPS * BATCH, OUTD, HID);
    }
}

// round 17
// speedup vs baseline: 1.0850x; 1.0850x over previous
#include <cuda_runtime.h>
#include <cuda_bf16.h>
#include <cstdint>

#define T_STEPS 1024
#define BATCH   64
#define DIN     256
#define HID     512
#define OUTD    256
#define G3      1536   // 3*HID
#define MROWS   (T_STEPS * BATCH)   // 65536

// ---------------- persistent scratch (device globals; no allocation) ----------
__device__ float g_xg[(size_t)MROWS * G3];             // ~402 MB
__device__ float g_hs[(size_t)MROWS * HID];            // ~134 MB
__device__ __align__(256) float g_h[2][HID * BATCH];   // k-major: [512][64]
__device__ unsigned int g_bar;
// bf16 split planes
__device__ __nv_bfloat16 g_xhi[(size_t)MROWS * DIN];
__device__ __nv_bfloat16 g_xlo[(size_t)MROWS * DIN];
__device__ __nv_bfloat16 g_hshi[(size_t)MROWS * HID];
__device__ __nv_bfloat16 g_hslo[(size_t)MROWS * HID];
__device__ __nv_bfloat16 g_wit_hi[G3 * DIN];           // Wi^T [1536][256]
__device__ __nv_bfloat16 g_wit_lo[G3 * DIN];
__device__ __nv_bfloat16 g_wot_hi[OUTD * HID];         // Wo^T [256][512]
__device__ __nv_bfloat16 g_wot_lo[OUTD * HID];

// ---------------- helpers -----------------------------------------------------
__device__ __forceinline__ void fma2(uint64_t& d, uint64_t a, uint64_t b) {
    asm("fma.rn.f32x2 %0, %1, %2, %0;" : "+l"(d) : "l"(a), "l"(b));
}
__device__ __forceinline__ uint64_t pack2(float lo, float hi) {
    uint64_t r;
    asm("mov.b64 %0, {%1, %2};" : "=l"(r) : "f"(lo), "f"(hi));
    return r;
}
__device__ __forceinline__ float2 unpack2(uint64_t v) {
    float2 f;
    asm("mov.b64 {%0, %1}, %2;" : "=f"(f.x), "=f"(f.y) : "l"(v));
    return f;
}
__device__ __forceinline__ uint32_t smem_u32(const void* p) {
    uint32_t a;
    asm("{ .reg .u64 t; cvta.to.shared.u64 t, %1; cvt.u32.u64 %0, t; }"
        : "=r"(a) : "l"(p));
    return a;
}
__device__ __forceinline__ void mbar_init(uint32_t mbar, uint32_t cnt) {
    asm volatile("mbarrier.init.shared.b64 [%0], %1;" :: "r"(mbar), "r"(cnt) : "memory");
}
__device__ __forceinline__ void mbar_expect_tx(uint32_t mbar, uint32_t bytes) {
    asm volatile("mbarrier.arrive.expect_tx.shared.b64 _, [%0], %1;"
                 :: "r"(mbar), "r"(bytes) : "memory");
}
__device__ __forceinline__ void mbar_wait(uint32_t mbar, uint32_t parity) {
    asm volatile(
        "{\n\t.reg .pred P;\n"
        "WL%=:\n\t"
        "mbarrier.try_wait.parity.acquire.cta.shared::cta.b64 P, [%0], %1, 0x989680;\n\t"
        "@P bra WD%=;\n\t"
        "bra WL%=;\n"
        "WD%=:\n\t}"
        :: "r"(mbar), "r"(parity) : "memory");
}
__device__ __forceinline__ void bulk_g2s_mc(uint32_t dst, const void* src,
                                            uint32_t bytes, uint32_t mbar,
                                            uint16_t mask) {
    asm volatile(
        "cp.async.bulk.shared::cluster.global.mbarrier::complete_tx::bytes"
        ".multicast::cluster [%0], [%1], %2, [%3], %4;"
        :: "r"(dst), "l"(src), "r"(bytes), "r"(mbar), "h"(mask) : "memory");
}
__device__ __forceinline__ void bar_arrive_release(unsigned int* p) {
    asm volatile("red.release.gpu.global.add.u32 [%0], 1;" :: "l"(p) : "memory");
}
__device__ __forceinline__ unsigned bar_load_acquire(unsigned int* p) {
    unsigned v;
    asm volatile("ld.acquire.gpu.global.u32 %0, [%1];" : "=r"(v) : "l"(p) : "memory");
    return v;
}
// ldmatrix x4 (b16, no trans)
__device__ __forceinline__ void ldm4(uint32_t addr, uint32_t* r) {
    asm volatile("ldmatrix.sync.aligned.m8n8.x4.shared.b16 {%0,%1,%2,%3}, [%4];"
                 : "=r"(r[0]), "=r"(r[1]), "=r"(r[2]), "=r"(r[3]) : "r"(addr));
}
// m16n8k16 bf16 mma, fp32 accum (generic sm_80+ HMMA — compiles for compute_103)
__device__ __forceinline__ void mma16816(float* c, const uint32_t* a,
                                         uint32_t b0, uint32_t b1) {
    asm volatile(
        "mma.sync.aligned.m16n8k16.row.col.f32.bf16.bf16.f32 "
        "{%0,%1,%2,%3}, {%4,%5,%6,%7}, {%8,%9}, {%0,%1,%2,%3};"
        : "+f"(c[0]), "+f"(c[1]), "+f"(c[2]), "+f"(c[3])
        : "r"(a[0]), "r"(a[1]), "r"(a[2]), "r"(a[3]), "r"(b0), "r"(b1));
}

// =============================================================================
// split kernels: fp32 -> (bf16 hi, bf16 lo)
// =============================================================================
__global__ void conv_split(const float* __restrict__ src,
                           __nv_bfloat16* __restrict__ hi,
                           __nv_bfloat16* __restrict__ lo, size_t n4)
{
    size_t stride = (size_t)gridDim.x * blockDim.x;
    for (size_t i = (size_t)blockIdx.x * blockDim.x + threadIdx.x; i < n4; i += stride) {
        float4 v = *(const float4*)(src + i * 4);
        __nv_bfloat16 hx = __float2bfloat16(v.x);
        __nv_bfloat16 hy = __float2bfloat16(v.y);
        __nv_bfloat16 hz = __float2bfloat16(v.z);
        __nv_bfloat16 hw = __float2bfloat16(v.w);
        __nv_bfloat162* h2 = (__nv_bfloat162*)(hi + i * 4);
        h2[0] = __nv_bfloat162(hx, hy);
        h2[1] = __nv_bfloat162(hz, hw);
        __nv_bfloat162* l2 = (__nv_bfloat162*)(lo + i * 4);
        l2[0] = __nv_bfloat162(__float2bfloat16(v.x - __bfloat162float(hx)),
                               __float2bfloat16(v.y - __bfloat162float(hy)));
        l2[1] = __nv_bfloat162(__float2bfloat16(v.z - __bfloat162float(hz)),
                               __float2bfloat16(v.w - __bfloat162float(hw)));
    }
}
// W[K][N] fp32 -> Wt hi/lo [N][K] bf16 (transpose + split)
__global__ void conv_wt(const float* __restrict__ W,
                        __nv_bfloat16* __restrict__ thi,
                        __nv_bfloat16* __restrict__ tlo, int K, int N)
{
    int idx = blockIdx.x * 256 + threadIdx.x;
    if (idx < K * N) {
        int k = idx / N, n = idx - k * N;
        float a = W[idx];
        __nv_bfloat16 h = __float2bfloat16(a);
        thi[(size_t)n * K + k] = h;
        tlo[(size_t)n * K + k] = __float2bfloat16(a - __bfloat162float(h));
    }
}

// =============================================================================
// bf16x3 split GEMM via mma.sync (legacy HMMA): C = A@B^T + bias
// A hi/lo [M][K] bf16 row-major; B hi/lo [N][K] bf16 row-major (pre-transposed).
// 128x128 tile, BK=32, 256 threads (8 warps, warp tile 32x64), 2 CTAs/SM.
// SMEM rows padded to 40 bf16 (80B): ldmatrix conflict-free (20-word stride).
// =============================================================================
#define SA_HI 0
#define SA_LO (128 * 80)            // 10240
#define SB_HI (2 * 128 * 80)        // 20480
#define SB_LO (3 * 128 * 80)        // 30720
#define GEMM_SMEM (4 * 128 * 80)    // 40960

__global__ void __launch_bounds__(256, 2) gemm_mma_bf16x3(
    const __nv_bfloat16* __restrict__ Ahi, const __nv_bfloat16* __restrict__ Alo,
    const __nv_bfloat16* __restrict__ Bhi, const __nv_bfloat16* __restrict__ Blo,
    const float* __restrict__ bias, float* __restrict__ C,
    int M, int N, int K)
{
    extern __shared__ char smem[];
    const uint32_t sb  = smem_u32(smem);
    const int tid  = threadIdx.x;
    const int wid  = tid >> 5;
    const int lane = tid & 31;
    const int wm   = wid & 3;          // warp row block (32 rows)
    const int wn   = wid >> 2;         // warp col block (64 cols)
    const int bm   = blockIdx.y * 128;
    const int bn   = blockIdx.x * 128;

    float acc[2][8][4];
#pragma unroll
    for (int i = 0; i < 2; i++)
#pragma unroll
        for (int j = 0; j < 8; j++)
#pragma unroll
            for (int q = 0; q < 4; q++) acc[i][j][q] = 0.f;

    // ldmatrix lane addressing (within-tile offsets)
    const uint32_t a_lane = (uint32_t)((lane & 15) * 80 + (lane >> 4) * 16);
    const uint32_t b_lane = (uint32_t)((((lane >> 4) * 8) + (lane & 7)) * 80 +
                                       ((lane >> 3) & 1) * 16);

    for (int k0 = 0; k0 < K; k0 += 32) {
        // ---- G2S: 4 tiles of 128 rows x 32 bf16, padded stride 40 ----
#pragma unroll
        for (int i = 0; i < 2; i++) {
            int idx = tid + i * 256;          // 0..511
            int row = idx >> 2, seg = idx & 3;
            uint32_t so = (uint32_t)(row * 80 + seg * 16);
            *(uint4*)(smem + SA_HI + so) =
                *(const uint4*)(Ahi + (size_t)(bm + row) * K + k0 + seg * 8);
            *(uint4*)(smem + SA_LO + so) =
                *(const uint4*)(Alo + (size_t)(bm + row) * K + k0 + seg * 8);
            *(uint4*)(smem + SB_HI + so) =
                *(const uint4*)(Bhi + (size_t)(bn + row) * K + k0 + seg * 8);
            *(uint4*)(smem + SB_LO + so) =
                *(const uint4*)(Blo + (size_t)(bn + row) * K + k0 + seg * 8);
        }
        __syncthreads();

#pragma unroll
        for (int s = 0; s < 2; s++) {          // two k16 steps per chunk
            const uint32_t koff = (uint32_t)(s * 32);   // 16 bf16 = 32B
            uint32_t ah[2][4], al[2][4];
            {
                uint32_t abase = sb + (uint32_t)(wm * 32 * 80) + a_lane + koff;
                ldm4(abase + SA_HI,            ah[0]);
                ldm4(abase + SA_HI + 16 * 80,  ah[1]);
                ldm4(abase + SA_LO,            al[0]);
                ldm4(abase + SA_LO + 16 * 80,  al[1]);
            }
#pragma unroll
            for (int np = 0; np < 4; np++) {   // 4 n16 pairs -> 8 n8 tiles
                uint32_t bbase = sb + (uint32_t)((wn * 64 + np * 16) * 80)
                               + b_lane + koff;
                uint32_t bh[4], bl[4];
                ldm4(bbase + SB_HI, bh);
                ldm4(bbase + SB_LO, bl);
#pragma unroll
                for (int mt = 0; mt < 2; mt++) {
#pragma unroll
                    for (int j = 0; j < 2; j++) {
                        float* c = acc[mt][np * 2 + j];
                        mma16816(c, ah[mt], bh[2 * j], bh[2 * j + 1]);
                        mma16816(c, ah[mt], bl[2 * j], bl[2 * j + 1]);
                        mma16816(c, al[mt], bh[2 * j], bh[2 * j + 1]);
                    }
                }
            }
        }
        __syncthreads();
    }

    // ---- epilogue: c0,c1 -> (row, col..col+1), c2,c3 -> (row+8, ..) ----
    const int r0 = bm + wm * 32 + (lane >> 2);
    const int c0 = bn + wn * 64 + 2 * (lane & 3);
#pragma unroll
    for (int mt = 0; mt < 2; mt++) {
#pragma unroll
        for (int nt = 0; nt < 8; nt++) {
            int row = r0 + mt * 16;
            int col = c0 + nt * 8;
            float b0 = bias[col], b1 = bias[col + 1];
            float2 v0 = make_float2(acc[mt][nt][0] + b0, acc[mt][nt][1] + b1);
            float2 v1 = make_float2(acc[mt][nt][2] + b0, acc[mt][nt][3] + b1);
            *(float2*)(C + (size_t)row * N + col)       = v0;
            *(float2*)(C + (size_t)(row + 8) * N + col) = v1;
        }
    }
}

// =============================================================================
// Persistent GRU scan v7 (unchanged, proven) — k-major h + 4-slice multicast
// =============================================================================
#define NT    512
#define RPAD2 193
#define HS_FLOATS  (HID * BATCH)
#define WS_FLOATS  (2 * 256 * 12)
#define RED_FLOATS (BATCH * RPAD2)
#define SCAN_SMEM  ((HS_FLOATS + WS_FLOATS + RED_FLOATS) * 4 + 32)
#define SLICE_BYTES (128 * BATCH * 4)

__global__ void __launch_bounds__(NT, 1) __cluster_dims__(4, 1, 1)
gru_scan(const float* __restrict__ Wh, const float* __restrict__ bhn)
{
    extern __shared__ float smemf[];
    float*  h_sm = smemf;
    float2* wsm2 = (float2*)(smemf + HS_FLOATS);
    float*  red  = smemf + HS_FLOATS + WS_FLOATS;
    uint64_t* mbar = (uint64_t*)(smemf + HS_FLOATS + WS_FLOATS + RED_FLOATS);

    const int tid = threadIdx.x;
    const int j0  = blockIdx.x * 4;

    uint32_t rank;
    asm("mov.u32 %0, %%cluster_ctarank;" : "=r"(rank));

    const uint32_t h_sm_a = smem_u32(h_sm);
    uint32_t mba[4];
#pragma unroll
    for (int s = 0; s < 4; s++) mba[s] = smem_u32(&mbar[s]);

    if (tid == 0)
#pragma unroll
        for (int s = 0; s < 4; s++) mbar_init(mba[s], 1);

    for (int i = tid; i < 256 * 12; i += NT) {
        int kp = i / 12, cc = i % 12;
        int jl = cc / 3, g = cc - jl * 3;
        int col = g * HID + j0 + jl;
        float2 v;
        v.x = Wh[(size_t)(2 * kp)     * G3 + col];
        v.y = Wh[(size_t)(2 * kp + 1) * G3 + col];
        wsm2[i] = v;
    }
    __syncthreads();
    asm volatile("barrier.cluster.arrive.aligned;" ::: "memory");
    asm volatile("barrier.cluster.wait.aligned;" ::: "memory");

    const int bb  = tid & 31;
    const int kq  = tid >> 5;
    const uint32_t mymb = mba[kq >> 2];
    const int rb  = tid >> 2;
    const int rjl = tid & 3;
    const float bh = bhn[j0 + rjl];

    const float*  hbase = h_sm + kq * 32 * BATCH + bb;
    const float2* wbase = wsm2 + (size_t)kq * 16 * 12;

    const unsigned nblk = gridDim.x;

    for (int t = 0; t < T_STEPS; t++) {
        const float* hread  = g_h[t & 1];
        float*       hwrite = g_h[(t & 1) ^ 1];

        if (tid == 0) {
#pragma unroll
            for (int s = 0; s < 4; s++) mbar_expect_tx(mba[s], SLICE_BYTES);
            bar_arrive_release(&g_bar);
            unsigned target = nblk * (unsigned)(t + 1);
            while (bar_load_acquire(&g_bar) < target) { }
            bulk_g2s_mc(h_sm_a + rank * SLICE_BYTES,
                        (const char*)hread + rank * SLICE_BYTES,
                        SLICE_BYTES, mba[rank], (uint16_t)0xF);
        }

        float xr = 0.f, xz = 0.f, xn = 0.f;
        if (tid < 256) {
            size_t xb = ((size_t)t * BATCH + rb) * G3 + j0 + rjl;
            xr = __ldcg(&g_xg[xb]);
            xz = __ldcg(&g_xg[xb + HID]);
            xn = __ldcg(&g_xg[xb + 2 * HID]);
        }

        mbar_wait(mymb, t & 1);

        uint64_t accA[12], accB[12];
#pragma unroll
        for (int cc = 0; cc < 12; cc++) { accA[cc] = 0ull; accB[cc] = 0ull; }

#pragma unroll
        for (int i = 0; i < 16; i++) {
            const float* hk = hbase + i * 2 * BATCH;
            uint64_t hA = pack2(hk[0],  hk[BATCH]);
            uint64_t hB = pack2(hk[32], hk[BATCH + 32]);
            const ulonglong2* w6 = (const ulonglong2*)(wbase + i * 12);
#pragma unroll
            for (int m = 0; m < 6; m++) {
                ulonglong2 wv = w6[m];
                fma2(accA[2 * m],     hA, wv.x);
                fma2(accA[2 * m + 1], hA, wv.y);
                fma2(accB[2 * m],     hB, wv.x);
                fma2(accB[2 * m + 1], hB, wv.y);
            }
        }

#pragma unroll
        for (int cc = 0; cc < 12; cc++) {
            float2 v = unpack2(accA[cc]);
            red[bb * RPAD2 + kq * 12 + cc] = v.x + v.y;
        }
#pragma unroll
        for (int cc = 0; cc < 12; cc++) {
            float2 v = unpack2(accB[cc]);
            red[(bb + 32) * RPAD2 + kq * 12 + cc] = v.x + v.y;
        }
        __syncthreads();

        if (tid < 256) {
            float hr = 0.f, hz = 0.f, hn = 0.f;
#pragma unroll
            for (int q = 0; q < 16; q++) {
                const float* rp = red + rb * RPAD2 + q * 12 + rjl * 3;
                hr += rp[0];
                hz += rp[1];
                hn += rp[2];
            }
            float rg = 1.f / (1.f + __expf(-(xr + hr)));
            float zg = 1.f / (1.f + __expf(-(xz + hz)));
            float ng = tanhf(xn + rg * (hn + bh));
            float hp = h_sm[(j0 + rjl) * BATCH + rb];
            float hnew = (1.f - zg) * ng + zg * hp;

            hwrite[(j0 + rjl) * BATCH + rb] = hnew;
            g_hs[((size_t)t * BATCH + rb) * HID + j0 + rjl] = hnew;
        }
        __syncthreads();
    }

    asm volatile("barrier.cluster.arrive.aligned;" ::: "memory");
    asm volatile("barrier.cluster.wait.aligned;" ::: "memory");
}

__global__ void seed_h0(const float* __restrict__ h0) {
    int i = blockIdx.x * 256 + threadIdx.x;
    int b = i >> 9, j = i & 511;
    g_h[0][j * BATCH + b] = h0[b * HID + j];
}

// =============================================================================
extern "C" void kernel_launch(void* const* d_in, const int* in_sizes, int n_in,
                              void* d_out, int out_size)
{
    const float* x   = (const float*)d_in[0];
    const float* Wi  = (const float*)d_in[1];
    const float* bi  = (const float*)d_in[2];
    const float* Wh  = (const float*)d_in[3];
    const float* bhn = (const float*)d_in[4];
    const float* Wo  = (const float*)d_in[5];
    const float* bo  = (const float*)d_in[6];
    const float* h0  = (const float*)d_in[7];
    float* out = (float*)d_out;

    void *xg_p, *hs_p, *bar_p;
    void *xhi_p, *xlo_p, *hshi_p, *hslo_p;
    void *wit_hi_p, *wit_lo_p, *wot_hi_p, *wot_lo_p;
    cudaGetSymbolAddress(&xg_p, g_xg);
    cudaGetSymbolAddress(&hs_p, g_hs);
    cudaGetSymbolAddress(&bar_p, g_bar);
    cudaGetSymbolAddress(&xhi_p, g_xhi);
    cudaGetSymbolAddress(&xlo_p, g_xlo);
    cudaGetSymbolAddress(&hshi_p, g_hshi);
    cudaGetSymbolAddress(&hslo_p, g_hslo);
    cudaGetSymbolAddress(&wit_hi_p, g_wit_hi);
    cudaGetSymbolAddress(&wit_lo_p, g_wit_lo);
    cudaGetSymbolAddress(&wot_hi_p, g_wot_hi);
    cudaGetSymbolAddress(&wot_lo_p, g_wot_lo);

    cudaFuncSetAttribute(gru_scan, cudaFuncAttributeMaxDynamicSharedMemorySize,
                         SCAN_SMEM);
    cudaFuncSetAttribute(gemm_mma_bf16x3,
                         cudaFuncAttributeMaxDynamicSharedMemorySize, GEMM_SMEM);

    cudaMemsetAsync(bar_p, 0, sizeof(unsigned), 0);
    seed_h0<<<128, 256>>>(h0);

    // bf16 splits
    conv_split<<<4096, 256>>>(x, (__nv_bfloat16*)xhi_p, (__nv_bfloat16*)xlo_p,
                              (size_t)MROWS * DIN / 4);
    conv_wt<<<(DIN * G3 + 255) / 256, 256>>>(Wi, (__nv_bfloat16*)wit_hi_p,
                                             (__nv_bfloat16*)wit_lo_p, DIN, G3);
    conv_wt<<<(HID * OUTD + 255) / 256, 256>>>(Wo, (__nv_bfloat16*)wot_hi_p,
                                               (__nv_bfloat16*)wot_lo_p, HID, OUTD);

    // 1) xg = x @ Wi + bi   (mma.sync bf16x3)
    {
        dim3 grid(G3 / 128, MROWS / 128);
        gemm_mma_bf16x3<<<grid, 256, GEMM_SMEM>>>(
            (const __nv_bfloat16*)xhi_p, (const __nv_bfloat16*)xlo_p,
            (const __nv_bfloat16*)wit_hi_p, (const __nv_bfloat16*)wit_lo_p,
            bi, (float*)xg_p, MROWS, G3, DIN);
    }

    // 2) persistent GRU scan (32 clusters of 4)
    gru_scan<<<HID / 4, NT, SCAN_SMEM>>>(Wh, bhn);

    // 3) out = hs @ Wo + bo  (mma.sync bf16x3)
    conv_split<<<4096, 256>>>((const float*)hs_p, (__nv_bfloat16*)hshi_p,
                              (__nv_bfloat16*)hslo_p, (size_t)MROWS * HID / 4);
    {
        dim3 grid(OUTD / 128, MROWS / 128);
        gemm_mma_bf16x3<<<grid, 256, GEMM_SMEM>>>(
            (const __nv_bfloat16*)hshi_p, (const __nv_bfloat16*)hslo_p,
            (const __nv_bfloat16*)wot_hi_p, (const __nv_bfloat16*)wot_lo_p,
            bo, out, MROWS, OUTD, HID);
    }
}